// round 16
// baseline (speedup 1.0000x reference)
#include <cuda_runtime.h>
#include <cuda_fp16.h>
#include <cstdint>

#define B_SZ 16384
#define H_SZ 1024
#define D_SZ 8
#define EPS_LN 1e-5f

// Scratch (no allocs allowed)
__device__ __align__(16) __half g_Ah[(size_t)B_SZ * H_SZ];    // hidden fp16, blocked
__device__ __align__(16) __half g_Wh[(size_t)H_SZ * H_SZ];    // W_push fp16, blocked
__device__ __align__(16) __half g_pushh[(size_t)B_SZ * H_SZ]; // pre-LN GEMM out (fp16)
__device__ float g_logits[B_SZ];                              // pop-gate logits (f32)

// Blocked layout: [blk128][kt(32)][r(128)][kk(32)] halfs.
static __device__ __forceinline__ size_t blk_off(int blk128, int kt, int r, int kk) {
    return ((size_t)blk128 * 32 + kt) * 4096 + (size_t)r * 32 + kk;
}

// ---------------------------------------------------------------------------
// Pre-convert + decide. Speculative prev gather (issued BEFORE the logit
// reduction, concurrent with hidden loads) breaks the serial DRAM chain.
// Output writes use streaming hints (no reuse) to protect g_Ah in L2.
// ---------------------------------------------------------------------------
__global__ __launch_bounds__(256) void preconv_kernel(
    const float* __restrict__ hidden,
    const float* __restrict__ W,
    const float* __restrict__ w_pop,
    const float* __restrict__ pointer,
    const float* __restrict__ b_pop,
    const float* __restrict__ stack,
    float* __restrict__ out)
{
    const int bid  = blockIdx.x;
    const int t    = threadIdx.x;
    const int half = t >> 7;
    const int tt   = t & 127;
    const int c0   = tt * 8;
    const int kt   = c0 >> 5, kk = c0 & 31;

    if (bid < B_SZ / 2) {
        const int row = bid * 2 + half;
        const size_t rowH = (size_t)row * H_SZ;
        const size_t srow = (size_t)row * (D_SZ * H_SZ);
        const float4 zero = make_float4(0.f, 0.f, 0.f, 0.f);

        // --- issue ALL long-latency loads up front (concurrent) ---
        const int ptr = (int)pointer[row];
        float4 p0 = zero, p1 = zero;
        if (ptr > 0) {   // speculative: consumed only if the decision needs it
            const float* pp = stack + srow + (size_t)(ptr - 1) * H_SZ + c0;
            p0 = __ldcs((const float4*)(pp));
            p1 = __ldcs((const float4*)(pp + 4));
        }
        const float4 h0 = *(const float4*)(hidden + rowH + c0);
        const float4 h1 = *(const float4*)(hidden + rowH + c0 + 4);
        const float4 w0 = *(const float4*)(w_pop + c0);
        const float4 w1 = *(const float4*)(w_pop + c0 + 4);

        float lacc = h0.x * w0.x + h0.y * w0.y + h0.z * w0.z + h0.w * w0.w
                   + h1.x * w1.x + h1.y * w1.y + h1.z * w1.z + h1.w * w1.w;

        __half2 v[4];
        v[0] = __floats2half2_rn(h0.x, h0.y);
        v[1] = __floats2half2_rn(h0.z, h0.w);
        v[2] = __floats2half2_rn(h1.x, h1.y);
        v[3] = __floats2half2_rn(h1.z, h1.w);
        *(uint4*)&g_Ah[blk_off(row >> 7, kt, row & 127, kk)] = *(uint4*)v;

#pragma unroll
        for (int off = 16; off > 0; off >>= 1)
            lacc += __shfl_xor_sync(0xffffffff, lacc, off);
        __shared__ float red[8];
        __shared__ float s_logit[2];
        if ((t & 31) == 0) red[t >> 5] = lacc;
        __syncthreads();
        if (tt == 0) {
            int w0i = half * 4;
            float lg = red[w0i] + red[w0i + 1] + red[w0i + 2] + red[w0i + 3];
            g_logits[row] = lg;
            s_logit[half] = lg;
        }
        __syncthreads();

        // ---- decision + GEMM-independent outputs ----
        const float logit = s_logit[half] + b_pop[0];
        const bool  is_pop  = logit > 0.0f;           // sigmoid(z)>0.5 <=> z>0
        const bool  do_pop  = is_pop && (ptr > 0);
        const bool  do_push = (!is_pop) && (ptr < D_SZ);

        const size_t ptr_off = (size_t)B_SZ * D_SZ * H_SZ;
        const size_t top_off = ptr_off + B_SZ;
        const size_t pop_off = top_off + (size_t)B_SZ * H_SZ;

        // popped: prev where do_pop, zeros elsewhere (all rows)
        __stcs((float4*)(out + pop_off + rowH + c0),     do_pop ? p0 : zero);
        __stcs((float4*)(out + pop_off + rowH + c0 + 4), do_pop ? p1 : zero);

        // top for non-push rows (push rows get y from fixup)
        if (!do_push) {
            __stcs((float4*)(out + top_off + rowH + c0),     (ptr > 0) ? p0 : zero);
            __stcs((float4*)(out + top_off + rowH + c0 + 4), (ptr > 0) ? p1 : zero);
        }

        if (tt == 0) {
            int np = do_pop ? (ptr - 1) : (do_push ? (ptr + 1) : ptr);
            out[ptr_off + row] = (float)np;
        }
    } else {
        const int n = (bid - B_SZ / 2) * 2 + half;
        const float4 a0 = *(const float4*)(W + (size_t)n * H_SZ + c0);
        const float4 a1 = *(const float4*)(W + (size_t)n * H_SZ + c0 + 4);
        __half2 v[4];
        v[0] = __floats2half2_rn(a0.x, a0.y);
        v[1] = __floats2half2_rn(a0.z, a0.w);
        v[2] = __floats2half2_rn(a1.x, a1.y);
        v[3] = __floats2half2_rn(a1.z, a1.w);
        *(uint4*)&g_Wh[blk_off(n >> 7, kt, n & 127, kk)] = *(uint4*)v;
    }
}

// ---------------------------------------------------------------------------
// Fused fp16 GEMM + software-pipelined stack copy. BYTE-IDENTICAL to R12.
// ---------------------------------------------------------------------------
#define ROWB 80
#define STAGE_B (128 * ROWB)   // 10240 bytes per operand stage

static __device__ __forceinline__ void cpa16(uint32_t dst, const void* src) {
    asm volatile("cp.async.cg.shared.global [%0], [%1], 16;" :: "r"(dst), "l"(src));
}
#define LDSM_X4(r0, r1, r2, r3, addr) \
    asm volatile("ldmatrix.sync.aligned.m8n8.x4.shared.b16 {%0,%1,%2,%3}, [%4];" \
                 : "=r"(r0), "=r"(r1), "=r"(r2), "=r"(r3) : "r"(addr))

__global__ __launch_bounds__(256, 2) void gemm_copy_kernel(
    const float* __restrict__ bias,
    const float* __restrict__ stack,
    float* __restrict__ out)
{
    __shared__ __align__(16) char As[2][STAGE_B];
    __shared__ __align__(16) char Bs[2][STAGE_B];

    const int tid  = threadIdx.x;
    const int warp = tid >> 5;
    const int lane = tid & 31;
    const int wm   = warp >> 2;       // 0..1 -> 64-row slab
    const int wn   = warp & 3;        // 0..3 -> 32-col slab
    const int bx   = blockIdx.x;      // N block (0..7)
    const int by   = blockIdx.y;      // M block (0..127)
    const int cta  = by * 8 + bx;

    const uint32_t sA = (uint32_t)__cvta_generic_to_shared(&As[0][0]);
    const uint32_t sB = (uint32_t)__cvta_generic_to_shared(&Bs[0][0]);

    const int lm   = lane >> 3;
    const int lrow = lane & 7;
    const uint32_t aoff = (uint32_t)((wm * 64 + (lm & 1) * 8 + lrow) * ROWB + (lm >> 1) * 16);

    const uint4* stk4 = (const uint4*)stack;
    uint4*       out4 = (uint4*)out;
    const size_t cbase = (size_t)cta * 32768 + tid;

    float acc[4][4][4];
#pragma unroll
    for (int i = 0; i < 4; i++)
#pragma unroll
        for (int j = 0; j < 4; j++)
#pragma unroll
            for (int k = 0; k < 4; k++) acc[i][j][k] = 0.0f;

    auto issue = [&](int kt, int buf) {
#pragma unroll
        for (int i = 0; i < 4; i++) {
            int idx = tid + i * 256;
            if (idx < 512) {
                int r = idx >> 2, ch = idx & 3;
                cpa16(sA + buf * STAGE_B + r * ROWB + ch * 16,
                      g_Ah + blk_off(by, kt, r, ch * 8));
            } else {
                int j2 = idx - 512;
                int r = j2 >> 2, ch = j2 & 3;
                cpa16(sB + buf * STAGE_B + r * ROWB + ch * 16,
                      g_Wh + blk_off(bx, kt, r, ch * 8));
            }
        }
        asm volatile("cp.async.commit_group;" ::: "memory");
    };

    issue(0, 0);
    issue(1, 1);

#pragma unroll 1
    for (int kt = 0; kt < 32; kt++) {
        const int buf = kt & 1;
        if (kt == 31) asm volatile("cp.async.wait_group 0;" ::: "memory");
        else          asm volatile("cp.async.wait_group 1;" ::: "memory");
        __syncthreads();

        const size_t p0 = cbase + (size_t)kt * 1024;
        uint4 c0v = stk4[p0];
        uint4 c1v = stk4[p0 + 256];
        uint4 c2v = stk4[p0 + 512];
        uint4 c3v = stk4[p0 + 768];

        const uint32_t aB = sA + buf * STAGE_B;
        const char*    b_base = Bs[buf];

#pragma unroll
        for (int ks = 0; ks < 2; ks++) {
            uint32_t afr[4][4];
#pragma unroll
            for (int tm = 0; tm < 4; tm++)
                LDSM_X4(afr[tm][0], afr[tm][1], afr[tm][2], afr[tm][3],
                        aB + aoff + tm * (16 * ROWB) + ks * 32);

#pragma unroll
            for (int nt = 0; nt < 4; nt++) {
                const char* q = b_base + (wn * 32 + nt * 8 + (lane >> 2)) * ROWB
                                       + ks * 32 + (lane & 3) * 4;
                uint32_t b0 = *(const uint32_t*)(q);
                uint32_t b1 = *(const uint32_t*)(q + 16);
#pragma unroll
                for (int tm = 0; tm < 4; tm++) {
                    asm volatile(
                        "mma.sync.aligned.m16n8k16.row.col.f32.f16.f16.f32 "
                        "{%0,%1,%2,%3}, {%4,%5,%6,%7}, {%8,%9}, {%0,%1,%2,%3};"
                        : "+f"(acc[tm][nt][0]), "+f"(acc[tm][nt][1]),
                          "+f"(acc[tm][nt][2]), "+f"(acc[tm][nt][3])
                        : "r"(afr[tm][0]), "r"(afr[tm][1]),
                          "r"(afr[tm][2]), "r"(afr[tm][3]),
                          "r"(b0), "r"(b1));
                }
            }
        }
        __syncthreads();
        if (kt + 2 < 32) issue(kt + 2, buf);

        out4[p0]       = c0v;
        out4[p0 + 256] = c1v;
        out4[p0 + 512] = c2v;
        out4[p0 + 768] = c3v;
    }

    // epilogue: + bias -> g_pushh (fp16)
#pragma unroll
    for (int tm = 0; tm < 4; tm++) {
        int r = by * 128 + wm * 64 + tm * 16 + (lane >> 2);
#pragma unroll
        for (int nt = 0; nt < 4; nt++) {
            int c = bx * 128 + wn * 32 + nt * 8 + (lane & 3) * 2;
            float2 bv = *(const float2*)(bias + c);
            __half2 h0 = __floats2half2_rn(acc[tm][nt][0] + bv.x,
                                           acc[tm][nt][1] + bv.y);
            __half2 h1 = __floats2half2_rn(acc[tm][nt][2] + bv.x,
                                           acc[tm][nt][3] + bv.y);
            *(__half2*)(g_pushh + (size_t)r * H_SZ + c)       = h0;
            *(__half2*)(g_pushh + (size_t)(r + 8) * H_SZ + c) = h1;
        }
    }
}

// ---------------------------------------------------------------------------
// Fixup (push rows only, early-exit otherwise). LN(g_pushh) -> top + scatter.
// ---------------------------------------------------------------------------
__global__ __launch_bounds__(256) void fixup_kernel(
    const float* __restrict__ pointer,
    const float* __restrict__ ln_g,
    const float* __restrict__ ln_b,
    const float* __restrict__ b_pop,
    float* __restrict__ out)
{
    const int row = blockIdx.x;

    const float logit = g_logits[row] + b_pop[0];
    const int   ptr   = (int)pointer[row];
    const bool  do_push = (logit <= 0.0f) && (ptr < D_SZ);
    if (!do_push) return;                       // uniform across block

    const int tid = threadIdx.x;
    const int c0  = tid * 4;
    const size_t rowH = (size_t)row * H_SZ;

    const uint2 xr = *(const uint2*)(g_pushh + rowH + c0);
    float2 f0 = __half22float2(*(const __half2*)&xr.x);
    float2 f1 = __half22float2(*(const __half2*)&xr.y);
    float4 x = make_float4(f0.x, f0.y, f1.x, f1.y);

    float s  = x.x + x.y + x.z + x.w;
    float ss = x.x * x.x + x.y * x.y + x.z * x.z + x.w * x.w;

#pragma unroll
    for (int off = 16; off > 0; off >>= 1) {
        s  += __shfl_xor_sync(0xffffffff, s,  off);
        ss += __shfl_xor_sync(0xffffffff, ss, off);
    }
    __shared__ float red[2][8];
    const int warp = tid >> 5, lane = tid & 31;
    if (lane == 0) { red[0][warp] = s; red[1][warp] = ss; }
    __syncthreads();
    float S = 0.f, SS = 0.f;
#pragma unroll
    for (int i = 0; i < 8; i++) { S += red[0][i]; SS += red[1][i]; }

    const float inv_h = 1.0f / (float)H_SZ;
    float mu  = S * inv_h;
    float var = SS * inv_h - mu * mu;
    float rs  = rsqrtf(var + EPS_LN);

    float4 g = *(const float4*)(ln_g + c0);
    float4 b = *(const float4*)(ln_b + c0);
    float4 y;
    y.x = (x.x - mu) * rs * g.x + b.x;
    y.y = (x.y - mu) * rs * g.y + b.y;
    y.z = (x.z - mu) * rs * g.z + b.z;
    y.w = (x.w - mu) * rs * g.w + b.w;

    const size_t srow = (size_t)row * (D_SZ * H_SZ);
    const size_t ptr_off = (size_t)B_SZ * D_SZ * H_SZ;
    const size_t top_off = ptr_off + B_SZ;

    *(float4*)(out + srow + (size_t)ptr * H_SZ + c0) = y;   // scatter push row
    *(float4*)(out + top_off + rowH + c0) = y;              // top = y
}

// ---------------------------------------------------------------------------
// Launch
// ---------------------------------------------------------------------------
extern "C" void kernel_launch(void* const* d_in, const int* in_sizes, int n_in,
                              void* d_out, int out_size)
{
    const float* hidden  = (const float*)d_in[0];
    const float* stack   = (const float*)d_in[1];
    const float* pointer = (const float*)d_in[2];
    const float* W_push  = (const float*)d_in[3];
    const float* b_push  = (const float*)d_in[4];
    const float* ln_g    = (const float*)d_in[5];
    const float* ln_b    = (const float*)d_in[6];
    const float* w_pop   = (const float*)d_in[7];
    const float* b_pop   = (const float*)d_in[8];
    float* out = (float*)d_out;

    preconv_kernel<<<B_SZ / 2 + H_SZ / 2, 256>>>(hidden, W_push, w_pop,
                                                 pointer, b_pop, stack, out);

    dim3 ggrid(H_SZ / 128, B_SZ / 128);   // (8, 128)
    gemm_copy_kernel<<<ggrid, 256>>>(b_push, stack, out);

    fixup_kernel<<<B_SZ, 256>>>(pointer, ln_g, ln_b, b_pop, out);
}

// round 17
// speedup vs baseline: 1.0348x; 1.0348x over previous
#include <cuda_runtime.h>
#include <cuda_fp16.h>
#include <cstdint>

#define B_SZ 16384
#define H_SZ 1024
#define D_SZ 8
#define EPS_LN 1e-5f

// Scratch (no allocs allowed)
__device__ __align__(16) __half g_Ah[(size_t)B_SZ * H_SZ];    // hidden fp16, blocked
__device__ __align__(16) __half g_Wh[(size_t)H_SZ * H_SZ];    // W_push fp16, blocked
__device__ __align__(16) __half g_pushh[(size_t)B_SZ * H_SZ]; // pre-LN GEMM out (fp16)
__device__ float g_logits[B_SZ];                              // pop-gate logits (f32)

// Blocked layout: [blk128][kt(32)][r(128)][kk(32)] halfs.
static __device__ __forceinline__ size_t blk_off(int blk128, int kt, int r, int kk) {
    return ((size_t)blk128 * 32 + kt) * 4096 + (size_t)r * 32 + kk;
}

// ---------------------------------------------------------------------------
// Pre-convert: f32 -> fp16 blocked + exact f32 pop-gate logits. (R12 version)
// ---------------------------------------------------------------------------
__global__ __launch_bounds__(256) void preconv_kernel(
    const float* __restrict__ hidden,
    const float* __restrict__ W,
    const float* __restrict__ w_pop)
{
    const int bid  = blockIdx.x;
    const int t    = threadIdx.x;
    const int half = t >> 7;
    const int tt   = t & 127;
    const int c0   = tt * 8;
    const int kt   = c0 >> 5, kk = c0 & 31;

    if (bid < B_SZ / 2) {
        const int row = bid * 2 + half;
        const float4 h0 = *(const float4*)(hidden + (size_t)row * H_SZ + c0);
        const float4 h1 = *(const float4*)(hidden + (size_t)row * H_SZ + c0 + 4);
        const float4 w0 = *(const float4*)(w_pop + c0);
        const float4 w1 = *(const float4*)(w_pop + c0 + 4);

        float lacc = h0.x * w0.x + h0.y * w0.y + h0.z * w0.z + h0.w * w0.w
                   + h1.x * w1.x + h1.y * w1.y + h1.z * w1.z + h1.w * w1.w;

        __half2 v[4];
        v[0] = __floats2half2_rn(h0.x, h0.y);
        v[1] = __floats2half2_rn(h0.z, h0.w);
        v[2] = __floats2half2_rn(h1.x, h1.y);
        v[3] = __floats2half2_rn(h1.z, h1.w);
        *(uint4*)&g_Ah[blk_off(row >> 7, kt, row & 127, kk)] = *(uint4*)v;

#pragma unroll
        for (int off = 16; off > 0; off >>= 1)
            lacc += __shfl_xor_sync(0xffffffff, lacc, off);
        __shared__ float red[8];
        if ((t & 31) == 0) red[t >> 5] = lacc;
        __syncthreads();
        if (tt == 0) {
            int w0i = half * 4;
            g_logits[row] = red[w0i] + red[w0i + 1] + red[w0i + 2] + red[w0i + 3];
        }
    } else {
        const int n = (bid - B_SZ / 2) * 2 + half;
        const float4 a0 = *(const float4*)(W + (size_t)n * H_SZ + c0);
        const float4 a1 = *(const float4*)(W + (size_t)n * H_SZ + c0 + 4);
        __half2 v[4];
        v[0] = __floats2half2_rn(a0.x, a0.y);
        v[1] = __floats2half2_rn(a0.z, a0.w);
        v[2] = __floats2half2_rn(a1.x, a1.y);
        v[3] = __floats2half2_rn(a1.z, a1.w);
        *(uint4*)&g_Wh[blk_off(n >> 7, kt, n & 127, kk)] = *(uint4*)v;
    }
}

// ---------------------------------------------------------------------------
// Fused fp16 GEMM + software-pipelined stack copy. BYTE-IDENTICAL to R12.
// ---------------------------------------------------------------------------
#define ROWB 80
#define STAGE_B (128 * ROWB)   // 10240 bytes per operand stage

static __device__ __forceinline__ void cpa16(uint32_t dst, const void* src) {
    asm volatile("cp.async.cg.shared.global [%0], [%1], 16;" :: "r"(dst), "l"(src));
}
#define LDSM_X4(r0, r1, r2, r3, addr) \
    asm volatile("ldmatrix.sync.aligned.m8n8.x4.shared.b16 {%0,%1,%2,%3}, [%4];" \
                 : "=r"(r0), "=r"(r1), "=r"(r2), "=r"(r3) : "r"(addr))

__global__ __launch_bounds__(256, 2) void gemm_copy_kernel(
    const float* __restrict__ bias,
    const float* __restrict__ stack,
    float* __restrict__ out)
{
    __shared__ __align__(16) char As[2][STAGE_B];
    __shared__ __align__(16) char Bs[2][STAGE_B];

    const int tid  = threadIdx.x;
    const int warp = tid >> 5;
    const int lane = tid & 31;
    const int wm   = warp >> 2;       // 0..1 -> 64-row slab
    const int wn   = warp & 3;        // 0..3 -> 32-col slab
    const int bx   = blockIdx.x;      // N block (0..7)
    const int by   = blockIdx.y;      // M block (0..127)
    const int cta  = by * 8 + bx;

    const uint32_t sA = (uint32_t)__cvta_generic_to_shared(&As[0][0]);
    const uint32_t sB = (uint32_t)__cvta_generic_to_shared(&Bs[0][0]);

    const int lm   = lane >> 3;
    const int lrow = lane & 7;
    const uint32_t aoff = (uint32_t)((wm * 64 + (lm & 1) * 8 + lrow) * ROWB + (lm >> 1) * 16);

    const uint4* stk4 = (const uint4*)stack;
    uint4*       out4 = (uint4*)out;
    const size_t cbase = (size_t)cta * 32768 + tid;

    float acc[4][4][4];
#pragma unroll
    for (int i = 0; i < 4; i++)
#pragma unroll
        for (int j = 0; j < 4; j++)
#pragma unroll
            for (int k = 0; k < 4; k++) acc[i][j][k] = 0.0f;

    auto issue = [&](int kt, int buf) {
#pragma unroll
        for (int i = 0; i < 4; i++) {
            int idx = tid + i * 256;
            if (idx < 512) {
                int r = idx >> 2, ch = idx & 3;
                cpa16(sA + buf * STAGE_B + r * ROWB + ch * 16,
                      g_Ah + blk_off(by, kt, r, ch * 8));
            } else {
                int j2 = idx - 512;
                int r = j2 >> 2, ch = j2 & 3;
                cpa16(sB + buf * STAGE_B + r * ROWB + ch * 16,
                      g_Wh + blk_off(bx, kt, r, ch * 8));
            }
        }
        asm volatile("cp.async.commit_group;" ::: "memory");
    };

    issue(0, 0);
    issue(1, 1);

#pragma unroll 1
    for (int kt = 0; kt < 32; kt++) {
        const int buf = kt & 1;
        if (kt == 31) asm volatile("cp.async.wait_group 0;" ::: "memory");
        else          asm volatile("cp.async.wait_group 1;" ::: "memory");
        __syncthreads();

        const size_t p0 = cbase + (size_t)kt * 1024;
        uint4 c0v = stk4[p0];
        uint4 c1v = stk4[p0 + 256];
        uint4 c2v = stk4[p0 + 512];
        uint4 c3v = stk4[p0 + 768];

        const uint32_t aB = sA + buf * STAGE_B;
        const char*    b_base = Bs[buf];

#pragma unroll
        for (int ks = 0; ks < 2; ks++) {
            uint32_t afr[4][4];
#pragma unroll
            for (int tm = 0; tm < 4; tm++)
                LDSM_X4(afr[tm][0], afr[tm][1], afr[tm][2], afr[tm][3],
                        aB + aoff + tm * (16 * ROWB) + ks * 32);

#pragma unroll
            for (int nt = 0; nt < 4; nt++) {
                const char* q = b_base + (wn * 32 + nt * 8 + (lane >> 2)) * ROWB
                                       + ks * 32 + (lane & 3) * 4;
                uint32_t b0 = *(const uint32_t*)(q);
                uint32_t b1 = *(const uint32_t*)(q + 16);
#pragma unroll
                for (int tm = 0; tm < 4; tm++) {
                    asm volatile(
                        "mma.sync.aligned.m16n8k16.row.col.f32.f16.f16.f32 "
                        "{%0,%1,%2,%3}, {%4,%5,%6,%7}, {%8,%9}, {%0,%1,%2,%3};"
                        : "+f"(acc[tm][nt][0]), "+f"(acc[tm][nt][1]),
                          "+f"(acc[tm][nt][2]), "+f"(acc[tm][nt][3])
                        : "r"(afr[tm][0]), "r"(afr[tm][1]),
                          "r"(afr[tm][2]), "r"(afr[tm][3]),
                          "r"(b0), "r"(b1));
                }
            }
        }
        __syncthreads();
        if (kt + 2 < 32) issue(kt + 2, buf);

        out4[p0]       = c0v;
        out4[p0 + 256] = c1v;
        out4[p0 + 512] = c2v;
        out4[p0 + 768] = c3v;
    }

    // epilogue: + bias -> g_pushh (fp16)
#pragma unroll
    for (int tm = 0; tm < 4; tm++) {
        int r = by * 128 + wm * 64 + tm * 16 + (lane >> 2);
#pragma unroll
        for (int nt = 0; nt < 4; nt++) {
            int c = bx * 128 + wn * 32 + nt * 8 + (lane & 3) * 2;
            float2 bv = *(const float2*)(bias + c);
            __half2 h0 = __floats2half2_rn(acc[tm][nt][0] + bv.x,
                                           acc[tm][nt][1] + bv.y);
            __half2 h1 = __floats2half2_rn(acc[tm][nt][2] + bv.x,
                                           acc[tm][nt][3] + bv.y);
            *(__half2*)(g_pushh + (size_t)r * H_SZ + c)       = h0;
            *(__half2*)(g_pushh + (size_t)(r + 8) * H_SZ + c) = h1;
        }
    }
}

// ---------------------------------------------------------------------------
// Fixup, branched per row:
//   push rows:  read g_pushh, LN -> top=y, popped=0, scatter y, pointer.
//   other rows: gather prev (if ptr>0) -> top/popped, pointer. No LN, no
//               g_pushh read. Saves ~35 MB + half the LN math vs R12.
// ---------------------------------------------------------------------------
__global__ __launch_bounds__(256) void fixup_kernel(
    const float* __restrict__ stack,
    const float* __restrict__ pointer,
    const float* __restrict__ ln_g,
    const float* __restrict__ ln_b,
    const float* __restrict__ b_pop,
    float* __restrict__ out)
{
    const int row = blockIdx.x;
    const int tid = threadIdx.x;
    const int c0  = tid * 4;
    const size_t rowH = (size_t)row * H_SZ;
    const size_t srow = (size_t)row * (D_SZ * H_SZ);
    const size_t ptr_off = (size_t)B_SZ * D_SZ * H_SZ;
    const size_t top_off = ptr_off + B_SZ;
    const size_t pop_off = top_off + (size_t)B_SZ * H_SZ;
    const float4 zero = make_float4(0.f, 0.f, 0.f, 0.f);

    const float logit = g_logits[row] + b_pop[0];
    const int   ptr   = (int)pointer[row];
    const bool  is_pop  = logit > 0.0f;             // sigmoid(z)>0.5 <=> z>0
    const bool  do_pop  = is_pop && (ptr > 0);
    const bool  do_push = (!is_pop) && (ptr < D_SZ);

    if (!do_push) {
        // top = prev if ptr>0 else 0 ; popped = prev if do_pop else 0
        float4 prev = zero;
        if (ptr > 0)
            prev = *(const float4*)(stack + srow + (size_t)(ptr - 1) * H_SZ + c0);
        *(float4*)(out + top_off + rowH + c0) = (ptr > 0) ? prev : zero;
        *(float4*)(out + pop_off + rowH + c0) = do_pop ? prev : zero;
        if (tid == 0) {
            int np = do_pop ? (ptr - 1) : ptr;
            out[ptr_off + row] = (float)np;
        }
        return;
    }

    // ---- push row: LayerNorm path ----
    const uint2 xr = *(const uint2*)(g_pushh + rowH + c0);
    float2 f0 = __half22float2(*(const __half2*)&xr.x);
    float2 f1 = __half22float2(*(const __half2*)&xr.y);
    float4 x = make_float4(f0.x, f0.y, f1.x, f1.y);

    float s  = x.x + x.y + x.z + x.w;
    float ss = x.x * x.x + x.y * x.y + x.z * x.z + x.w * x.w;

#pragma unroll
    for (int off = 16; off > 0; off >>= 1) {
        s  += __shfl_xor_sync(0xffffffff, s,  off);
        ss += __shfl_xor_sync(0xffffffff, ss, off);
    }
    __shared__ float red[2][8];
    const int warp = tid >> 5, lane = tid & 31;
    if (lane == 0) { red[0][warp] = s; red[1][warp] = ss; }
    __syncthreads();
    float S = 0.f, SS = 0.f;
#pragma unroll
    for (int i = 0; i < 8; i++) { S += red[0][i]; SS += red[1][i]; }

    const float inv_h = 1.0f / (float)H_SZ;
    float mu  = S * inv_h;
    float var = SS * inv_h - mu * mu;
    float rs  = rsqrtf(var + EPS_LN);

    float4 g = *(const float4*)(ln_g + c0);
    float4 b = *(const float4*)(ln_b + c0);
    float4 y;
    y.x = (x.x - mu) * rs * g.x + b.x;
    y.y = (x.y - mu) * rs * g.y + b.y;
    y.z = (x.z - mu) * rs * g.z + b.z;
    y.w = (x.w - mu) * rs * g.w + b.w;

    *(float4*)(out + srow + (size_t)ptr * H_SZ + c0) = y;   // scatter push row
    *(float4*)(out + top_off + rowH + c0) = y;              // top = y
    *(float4*)(out + pop_off + rowH + c0) = zero;           // popped = 0

    if (tid == 0)
        out[ptr_off + row] = (float)(ptr + 1);
}

// ---------------------------------------------------------------------------
// Launch
// ---------------------------------------------------------------------------
extern "C" void kernel_launch(void* const* d_in, const int* in_sizes, int n_in,
                              void* d_out, int out_size)
{
    const float* hidden  = (const float*)d_in[0];
    const float* stack   = (const float*)d_in[1];
    const float* pointer = (const float*)d_in[2];
    const float* W_push  = (const float*)d_in[3];
    const float* b_push  = (const float*)d_in[4];
    const float* ln_g    = (const float*)d_in[5];
    const float* ln_b    = (const float*)d_in[6];
    const float* w_pop   = (const float*)d_in[7];
    const float* b_pop   = (const float*)d_in[8];
    float* out = (float*)d_out;

    preconv_kernel<<<B_SZ / 2 + H_SZ / 2, 256>>>(hidden, W_push, w_pop);

    dim3 ggrid(H_SZ / 128, B_SZ / 128);   // (8, 128)
    gemm_copy_kernel<<<ggrid, 256>>>(b_push, stack, out);

    fixup_kernel<<<B_SZ, 256>>>(stack, pointer, ln_g, ln_b, b_pop, out);
}